// round 7
// baseline (speedup 1.0000x reference)
#include <cuda_runtime.h>
#include <cstddef>

typedef unsigned long long ull;

#define NIMG 8192
#define GFC 32
#define NBLK_FC 256                /* 256*32 = 8192 exact */

// Transposed activations: g_actT[k][img], k in [0,400)
__device__ __align__(16) float g_actT[(size_t)400 * NIMG];

// ---- f32x2 helpers (Blackwell packed fp32: 2 FMA per issue slot) ----------
__device__ __forceinline__ ull pk2(float lo, float hi) {
    ull r; asm("mov.b64 %0,{%1,%2};" : "=l"(r) : "f"(lo), "f"(hi)); return r;
}
__device__ __forceinline__ ull bc2(float v) { return pk2(v, v); }
__device__ __forceinline__ void fma2(ull& d, ull a, ull b) {
    asm("fma.rn.f32x2 %0,%1,%2,%3;" : "=l"(d) : "l"(a), "l"(b), "l"(d));
}
__device__ __forceinline__ float2 up2(ull v) {
    float2 r; asm("mov.b64 {%0,%1},%2;" : "=f"(r.x), "=f"(r.y) : "l"(v)); return r;
}

// ---------------------------------------------------------------------------
// Kernel 1: fused conv1->relu->pool1->conv2->relu->pool2, warp-per-image.
// conv1: 54 tasks of 4x4 outputs; conv2: 32 tasks of 3x6. All FMA as f32x2
// with output-column pairing (weights broadcast-packed per channel).
// ---------------------------------------------------------------------------
__global__ __launch_bounds__(256, 2) void conv_kernel(const float* __restrict__ x,
                                                      const float* __restrict__ w1,
                                                      const float* __restrict__ w2)
{
    __shared__ __align__(16) float s_w1[456];
    __shared__ __align__(16) float s_w2[2400];
    __shared__ __align__(16) float s_A[8][768];   // patch [3][16][16] -> p1 [6][10][12]
    __shared__ __align__(16) float s_B[8][880];   // c1 [6][12][12] -> c2 [16][6][8]
    __shared__ __align__(16) float s_out[3200];   // [k=400][img=8]

    const int tid  = threadIdx.x;
    const int wid  = tid >> 5;
    const int lane = tid & 31;
    const int img  = blockIdx.x * 8 + wid;

    for (int i = tid; i < 450; i += 256) s_w1[i] = w1[i];
    for (int i = tid; i < 2400; i += 256) s_w2[i] = w2[i];
    __syncthreads();

    float* A = s_A[wid];
    float* B = s_B[wid];

    const float* xb = x + (size_t)img * 3072;
    for (int i = lane; i < 768; i += 32) {
        int c  = i >> 8;
        int rr = (i >> 4) & 15;
        int cc = i & 15;
        A[i] = xb[c * 1024 + rr * 32 + cc];
    }
    __syncwarp();

    // ---- conv1 + relu: 54 tasks (oc x 3rt x 3ct), each 4 rows x 4 cols
    for (int t = lane; t < 54; t += 32) {
        int oc  = t / 9;
        int rem = t % 9;
        int r0  = (rem / 3) * 4;
        int c0  = (rem % 3) * 4;
        ull ac[4][2];
        #pragma unroll
        for (int i = 0; i < 4; i++) { ac[i][0] = bc2(0.f); ac[i][1] = bc2(0.f); }

        for (int c = 0; c < 3; c++) {
            const float* wb = &s_w1[(oc * 3 + c) * 25];
            ull ww[25];
            #pragma unroll
            for (int i = 0; i < 25; i++) ww[i] = bc2(wb[i]);
            const float* Ac = &A[c * 256];
            #pragma unroll
            for (int rr = 0; rr < 8; rr++) {
                const float* pr = &Ac[(r0 + rr) * 16 + c0];
                float4 v0 = *reinterpret_cast<const float4*>(pr);
                float4 v1 = *reinterpret_cast<const float4*>(pr + 4);
                ull pp[7];
                pp[0] = pk2(v0.x, v0.y); pp[1] = pk2(v0.y, v0.z);
                pp[2] = pk2(v0.z, v0.w); pp[3] = pk2(v0.w, v1.x);
                pp[4] = pk2(v1.x, v1.y); pp[5] = pk2(v1.y, v1.z);
                pp[6] = pk2(v1.z, v1.w);
                #pragma unroll
                for (int orow = 0; orow < 4; orow++) {
                    int uu = rr - orow;
                    if (uu >= 0 && uu < 5) {
                        #pragma unroll
                        for (int v = 0; v < 5; v++) {
                            fma2(ac[orow][0], pp[v],     ww[uu * 5 + v]);
                            fma2(ac[orow][1], pp[v + 2], ww[uu * 5 + v]);
                        }
                    }
                }
            }
        }
        #pragma unroll
        for (int i = 0; i < 4; i++) {
            float2 a0 = up2(ac[i][0]);
            float2 a1 = up2(ac[i][1]);
            float* dst = &B[(oc * 12 + r0 + i) * 12 + c0];
            dst[0] = fmaxf(a0.x, 0.f); dst[1] = fmaxf(a0.y, 0.f);
            dst[2] = fmaxf(a1.x, 0.f); dst[3] = fmaxf(a1.y, 0.f);
        }
    }
    __syncwarp();

    // ---- pool1 (stride-1 2x2, top-left 10x10) -> A as p1[6][10][12]
    for (int t = lane; t < 600; t += 32) {
        int oc = t / 100;
        int rr = (t % 100) / 10;
        int cc = t % 10;
        const float* c1 = &B[(oc * 12 + rr) * 12 + cc];
        A[(oc * 10 + rr) * 12 + cc] = fmaxf(fmaxf(c1[0], c1[1]), fmaxf(c1[12], c1[13]));
    }
    __syncwarp();

    // ---- conv2 + relu: 32 tasks = oc(16) x rowhalf(2), 3 rows x 6 cols
    {
        int oc = lane >> 1;
        int r0 = (lane & 1) * 3;
        ull ac[3][3];
        #pragma unroll
        for (int i = 0; i < 3; i++)
            #pragma unroll
            for (int j = 0; j < 3; j++) ac[i][j] = bc2(0.f);

        for (int c = 0; c < 6; c++) {
            const float* wb = &s_w2[(oc * 6 + c) * 25];
            ull ww[25];
            #pragma unroll
            for (int i = 0; i < 25; i++) ww[i] = bc2(wb[i]);
            #pragma unroll
            for (int rr = 0; rr < 7; rr++) {
                const float* pr = &A[(c * 10 + r0 + rr) * 12];
                float4 v0 = *reinterpret_cast<const float4*>(pr);
                float4 v1 = *reinterpret_cast<const float4*>(pr + 4);
                float p8 = pr[8], p9 = pr[9];
                ull pp[9];
                pp[0] = pk2(v0.x, v0.y); pp[1] = pk2(v0.y, v0.z);
                pp[2] = pk2(v0.z, v0.w); pp[3] = pk2(v0.w, v1.x);
                pp[4] = pk2(v1.x, v1.y); pp[5] = pk2(v1.y, v1.z);
                pp[6] = pk2(v1.z, v1.w); pp[7] = pk2(v1.w, p8);
                pp[8] = pk2(p8, p9);
                #pragma unroll
                for (int orow = 0; orow < 3; orow++) {
                    int uu = rr - orow;
                    if (uu >= 0 && uu < 5) {
                        #pragma unroll
                        for (int v = 0; v < 5; v++) {
                            ull w = ww[uu * 5 + v];
                            fma2(ac[orow][0], pp[v],     w);
                            fma2(ac[orow][1], pp[v + 2], w);
                            fma2(ac[orow][2], pp[v + 4], w);
                        }
                    }
                }
            }
        }
        #pragma unroll
        for (int i = 0; i < 3; i++) {
            float* dst = &B[(oc * 6 + r0 + i) * 8];
            #pragma unroll
            for (int jp = 0; jp < 3; jp++) {
                float2 v = up2(ac[i][jp]);
                dst[2 * jp]     = fmaxf(v.x, 0.f);
                dst[2 * jp + 1] = fmaxf(v.y, 0.f);
            }
        }
    }
    __syncwarp();

    // ---- pool2 -> s_out[k][8]
    for (int t = lane; t < 400; t += 32) {
        int oc = t / 25;
        int rr = (t % 25) / 5;
        int cc = t % 5;
        const float* c2 = &B[(oc * 6 + rr) * 8 + cc];
        s_out[t * 8 + wid] = fmaxf(fmaxf(c2[0], c2[1]), fmaxf(c2[8], c2[9]));
    }
    __syncthreads();

    const int img0 = blockIdx.x * 8;
    for (int k = tid; k < 400; k += 256) {
        float4 v0 = *reinterpret_cast<const float4*>(&s_out[k * 8]);
        float4 v1 = *reinterpret_cast<const float4*>(&s_out[k * 8 + 4]);
        float* dst = &g_actT[(size_t)k * NIMG + img0];
        *reinterpret_cast<float4*>(dst)     = v0;
        *reinterpret_cast<float4*>(dst + 4) = v1;
    }
}

// ---------------------------------------------------------------------------
// Kernel 2: fused fc1(relu) -> fc2(relu) -> fc3, all FMA as f32x2.
// 256 blocks x 256 threads; 32 images per block (exact, no tail).
// fc1: 8img x 2out tiles (240 threads); images are the packed f32x2 lanes
// (LDS.128 of actT gives pairs for free), weights scalar-broadcast.
// w1 kept natural [o][k] layout (no transpose), double-buffered chunks of 20.
// ---------------------------------------------------------------------------
#define WCH 20
#define NCH 20
#define WST 21
#define NPREFW 10   /* ceil(120*20/256) */
#define NPREFA 3    /* ceil(20*32/256)  */

__global__ __launch_bounds__(256, 2) void fc_kernel(const float* __restrict__ fw1,
                                                    const float* __restrict__ fb1,
                                                    const float* __restrict__ fw2,
                                                    const float* __restrict__ fb2,
                                                    const float* __restrict__ fw3,
                                                    const float* __restrict__ fb3,
                                                    float* __restrict__ out)
{
    extern __shared__ __align__(16) float sm[];
    float* s_act = sm;                       // 2 x [20][32]  = 1280
    float* s_w1c = s_act + 1280;             // 2 x [120][21] = 5040
    float* s_h1T = s_w1c + 5040;             // [120][32]     = 3840
    float* s_w2T = s_h1T + 3840;             // [120][84]     = 10080
    float* s_w3  = s_w2T + 10080;            // 840
    float* s_b1  = s_w3 + 840;               // 120
    float* s_b2  = s_b1 + 120;               // 84
    float* s_b3  = s_b2 + 84;                // 12 (pad)
    float* s_h2  = sm;                       // alias act+w1c after fc1: [32][84]

    const int tid  = threadIdx.x;
    const int img0 = blockIdx.x * GFC;

    // stage w2 transposed [k][84], w3, biases
    for (int i = tid; i < 120 * 84; i += 256) {
        int o = i / 120, k = i % 120;
        s_w2T[k * 84 + o] = fw2[i];
    }
    for (int i = tid; i < 840; i += 256) s_w3[i] = fw3[i];
    if (tid < 120) s_b1[tid] = fb1[tid];
    else if (tid < 204) s_b2[tid - 120] = fb2[tid - 120];
    else if (tid < 214) s_b3[tid - 204] = fb3[tid - 204];

    // ---- fc1: [32,400] x [400,120]^T; tile 8img x 2out; 240 active threads
    const int i0 = (tid & 3) * 8;        // image offset
    const int o0 = (tid >> 2) * 2;       // output offset (0..118)
    const bool active = (tid < 240);
    ull ac0[4], ac1[4];
    #pragma unroll
    for (int p = 0; p < 4; p++) { ac0[p] = bc2(0.f); ac1[p] = bc2(0.f); }

    float prw[NPREFW];
    float pra[NPREFA];

    // chunk 0 -> regs -> buf0
    #pragma unroll
    for (int j = 0; j < NPREFW; j++) {
        int i = tid + j * 256;
        if (i < 2400) prw[j] = fw1[(i / WCH) * 400 + (i % WCH)];
    }
    #pragma unroll
    for (int j = 0; j < NPREFA; j++) {
        int i = tid + j * 256;
        if (i < 640) pra[j] = g_actT[(size_t)(i / 32) * NIMG + img0 + (i & 31)];
    }
    #pragma unroll
    for (int j = 0; j < NPREFW; j++) {
        int i = tid + j * 256;
        if (i < 2400) s_w1c[(i / WCH) * WST + (i % WCH)] = prw[j];
    }
    #pragma unroll
    for (int j = 0; j < NPREFA; j++) {
        int i = tid + j * 256;
        if (i < 640) s_act[i] = pra[j];
    }
    // chunk 1 -> regs
    #pragma unroll
    for (int j = 0; j < NPREFW; j++) {
        int i = tid + j * 256;
        if (i < 2400) prw[j] = fw1[(i / WCH) * 400 + WCH + (i % WCH)];
    }
    #pragma unroll
    for (int j = 0; j < NPREFA; j++) {
        int i = tid + j * 256;
        if (i < 640) pra[j] = g_actT[(size_t)(WCH + i / 32) * NIMG + img0 + (i & 31)];
    }
    __syncthreads();

    for (int ch = 0; ch < NCH; ch++) {
        const float* wbuf = s_w1c + (ch & 1) * 2520;
        const float* abuf = s_act + (ch & 1) * 640;
        if (active) {
            #pragma unroll 5
            for (int kk = 0; kk < WCH; kk++) {
                ull ww0 = bc2(wbuf[o0 * WST + kk]);
                ull ww1 = bc2(wbuf[o0 * WST + WST + kk]);
                const ull* ap = reinterpret_cast<const ull*>(&abuf[kk * 32 + i0]);
                #pragma unroll
                for (int p = 0; p < 4; p++) {
                    ull a = ap[p];
                    fma2(ac0[p], a, ww0);
                    fma2(ac1[p], a, ww1);
                }
            }
        }
        if (ch < NCH - 1) {
            float* nw = s_w1c + ((ch + 1) & 1) * 2520;
            float* na = s_act + ((ch + 1) & 1) * 640;
            #pragma unroll
            for (int j = 0; j < NPREFW; j++) {
                int i = tid + j * 256;
                if (i < 2400) nw[(i / WCH) * WST + (i % WCH)] = prw[j];
            }
            #pragma unroll
            for (int j = 0; j < NPREFA; j++) {
                int i = tid + j * 256;
                if (i < 640) na[i] = pra[j];
            }
            if (ch < NCH - 2) {
                const int kb = (ch + 2) * WCH;
                #pragma unroll
                for (int j = 0; j < NPREFW; j++) {
                    int i = tid + j * 256;
                    if (i < 2400) prw[j] = fw1[(i / WCH) * 400 + kb + (i % WCH)];
                }
                #pragma unroll
                for (int j = 0; j < NPREFA; j++) {
                    int i = tid + j * 256;
                    if (i < 640) pra[j] = g_actT[(size_t)(kb + i / 32) * NIMG + img0 + (i & 31)];
                }
            }
        }
        __syncthreads();
    }
    // bias + relu -> s_h1T[o][img]
    if (active) {
        float b0 = s_b1[o0], b1 = s_b1[o0 + 1];
        #pragma unroll
        for (int p = 0; p < 4; p++) {
            float2 v0 = up2(ac0[p]);
            float2 v1 = up2(ac1[p]);
            s_h1T[o0 * 32 + i0 + 2 * p]           = fmaxf(v0.x + b0, 0.f);
            s_h1T[o0 * 32 + i0 + 2 * p + 1]       = fmaxf(v0.y + b0, 0.f);
            s_h1T[(o0 + 1) * 32 + i0 + 2 * p]     = fmaxf(v1.x + b1, 0.f);
            s_h1T[(o0 + 1) * 32 + i0 + 2 * p + 1] = fmaxf(v1.y + b1, 0.f);
        }
    }
    __syncthreads();

    // ---- fc2: [32,120] x [120,84]^T; tile 4img x 4out; 168 active threads
    if (tid < 168) {
        int ii0 = (tid & 7) * 4;     // image offset (0..28)
        int oo0 = (tid >> 3) * 4;    // output offset (0..80)
        ull c2[4][2];
        #pragma unroll
        for (int oo = 0; oo < 4; oo++) { c2[oo][0] = bc2(0.f); c2[oo][1] = bc2(0.f); }
        #pragma unroll 6
        for (int k = 0; k < 120; k++) {
            float4 w = *reinterpret_cast<const float4*>(&s_w2T[k * 84 + oo0]);
            const ull* hp = reinterpret_cast<const ull*>(&s_h1T[k * 32 + ii0]);
            ull h0 = hp[0], h1 = hp[1];
            ull ww;
            ww = bc2(w.x); fma2(c2[0][0], h0, ww); fma2(c2[0][1], h1, ww);
            ww = bc2(w.y); fma2(c2[1][0], h0, ww); fma2(c2[1][1], h1, ww);
            ww = bc2(w.z); fma2(c2[2][0], h0, ww); fma2(c2[2][1], h1, ww);
            ww = bc2(w.w); fma2(c2[3][0], h0, ww); fma2(c2[3][1], h1, ww);
        }
        #pragma unroll
        for (int oo = 0; oo < 4; oo++) {
            float b = s_b2[oo0 + oo];
            #pragma unroll
            for (int ip = 0; ip < 2; ip++) {
                float2 v = up2(c2[oo][ip]);
                s_h2[(ii0 + 2 * ip) * 84 + oo0 + oo]     = fmaxf(v.x + b, 0.f);
                s_h2[(ii0 + 2 * ip + 1) * 84 + oo0 + oo] = fmaxf(v.y + b, 0.f);
            }
        }
    }
    __syncthreads();

    // ---- fc3: [32,84] x [84,10]^T -> out
    for (int t = tid; t < GFC * 10; t += 256) {
        int o  = t % 10;
        int im = t / 10;
        float a = s_b3[o];
        #pragma unroll
        for (int k = 0; k < 84; k += 4) {
            float4 h = *reinterpret_cast<const float4*>(&s_h2[im * 84 + k]);
            float4 w = *reinterpret_cast<const float4*>(&s_w3[o * 84 + k]);
            a += h.x * w.x + h.y * w.y + h.z * w.z + h.w * w.w;
        }
        out[(img0 + im) * 10 + o] = a;
    }
}

extern "C" void kernel_launch(void* const* d_in, const int* in_sizes, int n_in,
                              void* d_out, int out_size)
{
    const float* x   = (const float*)d_in[0];
    const float* w1  = (const float*)d_in[1];
    const float* w2  = (const float*)d_in[2];
    const float* fw1 = (const float*)d_in[3];
    const float* fb1 = (const float*)d_in[4];
    const float* fw2 = (const float*)d_in[5];
    const float* fb2 = (const float*)d_in[6];
    const float* fw3 = (const float*)d_in[7];
    const float* fb3 = (const float*)d_in[8];
    float* out = (float*)d_out;

    const int FC_SMEM = (1280 + 5040 + 3840 + 10080 + 840 + 120 + 84 + 12) *
                        (int)sizeof(float);
    cudaFuncSetAttribute(fc_kernel, cudaFuncAttributeMaxDynamicSharedMemorySize,
                         FC_SMEM);

    conv_kernel<<<NIMG / 8, 256>>>(x, w1, w2);
    fc_kernel<<<NBLK_FC, 256, FC_SMEM>>>(fw1, fb1, fw2, fb2, fw3, fb3, out);
}

// round 9
// speedup vs baseline: 1.1344x; 1.1344x over previous
#include <cuda_runtime.h>
#include <cstddef>

#define NIMG 8192
#define ACT_STRIDE 8256            /* >= 147*56 = 8232; 16B-aligned rows */
#define GFC 56
#define NBLK_FC 147

// Transposed activations: g_actT[k][img], k in [0,400). Tail stays zero.
__device__ __align__(16) float g_actT[(size_t)400 * ACT_STRIDE];

// ---------------------------------------------------------------------------
// Kernel 1: fused conv1->relu->pool1->conv2->relu->pool2 (Round-6 version)
// WARP-PER-IMAGE: 256 threads = 8 warps = 8 images per block.
// ---------------------------------------------------------------------------
__global__ __launch_bounds__(256) void conv_kernel(const float* __restrict__ x,
                                                   const float* __restrict__ w1,
                                                   const float* __restrict__ w2)
{
    __shared__ __align__(16) float s_w1[456];
    __shared__ __align__(16) float s_w2[2400];
    __shared__ __align__(16) float s_A[8][768];
    __shared__ __align__(16) float s_B[8][880];
    __shared__ __align__(16) float s_out[3200];

    const int tid  = threadIdx.x;
    const int wid  = tid >> 5;
    const int lane = tid & 31;
    const int img  = blockIdx.x * 8 + wid;

    for (int i = tid; i < 450; i += 256) s_w1[i] = w1[i];
    for (int i = tid; i < 2400; i += 256) s_w2[i] = w2[i];
    __syncthreads();

    float* A = s_A[wid];
    float* B = s_B[wid];

    const float* xb = x + (size_t)img * 3072;
    for (int i = lane; i < 768; i += 32) {
        int c  = i >> 8;
        int rr = (i >> 4) & 15;
        int cc = i & 15;
        A[i] = xb[c * 1024 + rr * 32 + cc];
    }
    __syncwarp();

    // conv1 + relu: 96 tasks, each 3x3 outputs; sliding-row form
    #pragma unroll
    for (int pass = 0; pass < 3; pass++) {
        int u   = lane + pass * 32;
        int oc  = u >> 4;
        int rem = u & 15;
        int r0  = (rem >> 2) * 3;
        int c0  = (rem & 3) * 3;
        float acc[3][3];
        #pragma unroll
        for (int i = 0; i < 3; i++)
            #pragma unroll
            for (int j = 0; j < 3; j++) acc[i][j] = 0.f;

        for (int c = 0; c < 3; c++) {
            float wreg[25];
            const float* wb = &s_w1[(oc * 3 + c) * 25];
            #pragma unroll
            for (int i = 0; i < 25; i++) wreg[i] = wb[i];
            const float* Ac = &A[c * 256];
            #pragma unroll
            for (int rr = 0; rr < 7; rr++) {
                float p[7];
                const float* pr = &Ac[(r0 + rr) * 16 + c0];
                #pragma unroll
                for (int j = 0; j < 7; j++) p[j] = pr[j];
                #pragma unroll
                for (int orow = 0; orow < 3; orow++) {
                    int uu = rr - orow;
                    if (uu >= 0 && uu < 5) {
                        #pragma unroll
                        for (int v = 0; v < 5; v++) {
                            float w = wreg[uu * 5 + v];
                            #pragma unroll
                            for (int j = 0; j < 3; j++)
                                acc[orow][j] += p[v + j] * w;
                        }
                    }
                }
            }
        }
        #pragma unroll
        for (int orow = 0; orow < 3; orow++)
            #pragma unroll
            for (int j = 0; j < 3; j++)
                B[(oc * 12 + r0 + orow) * 12 + c0 + j] = fmaxf(acc[orow][j], 0.f);
    }
    __syncwarp();

    for (int t = lane; t < 600; t += 32) {
        int oc = t / 100;
        int rr = (t % 100) / 10;
        int cc = t % 10;
        const float* c1 = &B[(oc * 12 + rr) * 12 + cc];
        A[(oc * 10 + rr) * 12 + cc] = fmaxf(fmaxf(c1[0], c1[1]), fmaxf(c1[12], c1[13]));
    }
    __syncwarp();

    // conv2 + relu: 32 tasks = oc(16) x rowhalf(2), weights in regs
    {
        int oc = lane >> 1;
        int r0 = (lane & 1) * 3;
        float acc[3][6];
        #pragma unroll
        for (int i = 0; i < 3; i++)
            #pragma unroll
            for (int j = 0; j < 6; j++) acc[i][j] = 0.f;

        for (int c = 0; c < 6; c++) {
            float wreg[25];
            const float* wb = &s_w2[(oc * 6 + c) * 25];
            #pragma unroll
            for (int i = 0; i < 25; i++) wreg[i] = wb[i];
            #pragma unroll
            for (int rr = 0; rr < 7; rr++) {
                const float* pr = &A[(c * 10 + r0 + rr) * 12];
                float p[10];
                float4 v0 = *reinterpret_cast<const float4*>(&pr[0]);
                float4 v1 = *reinterpret_cast<const float4*>(&pr[4]);
                p[0] = v0.x; p[1] = v0.y; p[2] = v0.z; p[3] = v0.w;
                p[4] = v1.x; p[5] = v1.y; p[6] = v1.z; p[7] = v1.w;
                p[8] = pr[8]; p[9] = pr[9];
                #pragma unroll
                for (int orow = 0; orow < 3; orow++) {
                    int uu = rr - orow;
                    if (uu >= 0 && uu < 5) {
                        #pragma unroll
                        for (int v = 0; v < 5; v++) {
                            float w = wreg[uu * 5 + v];
                            #pragma unroll
                            for (int j = 0; j < 6; j++)
                                acc[orow][j] += p[v + j] * w;
                        }
                    }
                }
            }
        }
        #pragma unroll
        for (int orow = 0; orow < 3; orow++)
            #pragma unroll
            for (int j = 0; j < 6; j++)
                B[(oc * 6 + r0 + orow) * 8 + j] = fmaxf(acc[orow][j], 0.f);
    }
    __syncwarp();

    for (int t = lane; t < 400; t += 32) {
        int oc = t / 25;
        int rr = (t % 25) / 5;
        int cc = t % 5;
        const float* c2 = &B[(oc * 6 + rr) * 8 + cc];
        s_out[t * 8 + wid] = fmaxf(fmaxf(c2[0], c2[1]), fmaxf(c2[8], c2[9]));
    }
    __syncthreads();

    const int img0 = blockIdx.x * 8;
    for (int k = tid; k < 400; k += 256) {
        float4 v0 = *reinterpret_cast<const float4*>(&s_out[k * 8]);
        float4 v1 = *reinterpret_cast<const float4*>(&s_out[k * 8 + 4]);
        float* dst = &g_actT[(size_t)k * ACT_STRIDE + img0];
        *reinterpret_cast<float4*>(dst)     = v0;
        *reinterpret_cast<float4*>(dst + 4) = v1;
    }
}

// ---------------------------------------------------------------------------
// Kernel 2: fused fc1(relu) -> fc2(relu) -> fc3
// 147 blocks x 256 threads; 56 images per block; ~100 KB smem.
// fc1: 8img x 4out register tiles (210 active) -> 3 LDS.128 per 32 FFMA;
// acts + w1 double-buffered in k-chunks of 20 with register prefetch.
// ---------------------------------------------------------------------------
#define WCH 20
#define NCH 20
#define W1STRIDE 124
#define NPREFW 10   /* ceil(20*120/256) */
#define NPREFA 5    /* ceil(20*56/256)  */

__global__ __launch_bounds__(256) void fc_kernel(const float* __restrict__ fw1,
                                                 const float* __restrict__ fb1,
                                                 const float* __restrict__ fw2,
                                                 const float* __restrict__ fb2,
                                                 const float* __restrict__ fw3,
                                                 const float* __restrict__ fb3,
                                                 float* __restrict__ out)
{
    extern __shared__ __align__(16) float sm[];
    float* s_act  = sm;                           // 2 x [20][56]  = 2240
    float* s_w1c  = s_act + 2 * WCH * GFC;        // 2 x [20][124] = 4960
    float* s_h1T  = s_w1c + 2 * WCH * W1STRIDE;   // [120][56]     = 6720
    float* s_w2T  = s_h1T + 120 * GFC;            // [120][84]     = 10080
    float* s_w3   = s_w2T + 120 * 84;             // 840
    float* s_b1   = s_w3 + 840;                   // 120
    float* s_b2   = s_b1 + 120;                   // 84
    float* s_b3   = s_b2 + 84;                    // 12 (pad)
    float* s_h2   = sm;                           // alias after fc1: [56][84]=4704

    const int tid  = threadIdx.x;
    const int img0 = blockIdx.x * GFC;

    // stage w2 transposed [k][84] (coalesced LDG), w3, biases
    for (int i = tid; i < 120 * 84; i += 256) {
        int o = i / 120, k = i % 120;
        s_w2T[k * 84 + o] = fw2[i];
    }
    for (int i = tid; i < 840; i += 256) s_w3[i] = fw3[i];
    if (tid < 120) s_b1[tid] = fb1[tid];
    else if (tid < 204) s_b2[tid - 120] = fb2[tid - 120];
    else if (tid < 214) s_b3[tid - 204] = fb3[tid - 204];

    // ---- fc1: [56,400] x [400,120]^T; 8img x 4out tiles; 210 active threads
    const int o0 = (tid % 30) * 4;
    const int i0 = (tid / 30) * 8;
    const bool active = (tid < 210);
    float acc[8][4];
    #pragma unroll
    for (int i = 0; i < 8; i++)
        #pragma unroll
        for (int j = 0; j < 4; j++) acc[i][j] = 0.f;

    float prw[NPREFW];
    float pra[NPREFA];

    // chunk 0 -> regs -> buf0
    #pragma unroll
    for (int j = 0; j < NPREFW; j++) {
        int i = tid + j * 256;
        if (i < 2400) prw[j] = fw1[(i / WCH) * 400 + (i % WCH)];
    }
    #pragma unroll
    for (int j = 0; j < NPREFA; j++) {
        int i = tid + j * 256;
        if (i < WCH * GFC) pra[j] = g_actT[(size_t)(i / GFC) * ACT_STRIDE + img0 + (i % GFC)];
    }
    #pragma unroll
    for (int j = 0; j < NPREFW; j++) {
        int i = tid + j * 256;
        if (i < 2400) s_w1c[(i % WCH) * W1STRIDE + (i / WCH)] = prw[j];
    }
    #pragma unroll
    for (int j = 0; j < NPREFA; j++) {
        int i = tid + j * 256;
        if (i < WCH * GFC) s_act[i] = pra[j];
    }
    // chunk 1 -> regs
    #pragma unroll
    for (int j = 0; j < NPREFW; j++) {
        int i = tid + j * 256;
        if (i < 2400) prw[j] = fw1[(i / WCH) * 400 + WCH + (i % WCH)];
    }
    #pragma unroll
    for (int j = 0; j < NPREFA; j++) {
        int i = tid + j * 256;
        if (i < WCH * GFC) pra[j] = g_actT[(size_t)(WCH + i / GFC) * ACT_STRIDE + img0 + (i % GFC)];
    }
    __syncthreads();

    for (int ch = 0; ch < NCH; ch++) {
        const float* wbuf = s_w1c + (ch & 1) * (WCH * W1STRIDE);
        const float* abuf = s_act + (ch & 1) * (WCH * GFC);
        if (active) {
            #pragma unroll 5
            for (int kk = 0; kk < WCH; kk++) {
                float4 w  = *reinterpret_cast<const float4*>(&wbuf[kk * W1STRIDE + o0]);
                float4 a0 = *reinterpret_cast<const float4*>(&abuf[kk * GFC + i0]);
                float4 a1 = *reinterpret_cast<const float4*>(&abuf[kk * GFC + i0 + 4]);
                acc[0][0] += a0.x * w.x; acc[0][1] += a0.x * w.y; acc[0][2] += a0.x * w.z; acc[0][3] += a0.x * w.w;
                acc[1][0] += a0.y * w.x; acc[1][1] += a0.y * w.y; acc[1][2] += a0.y * w.z; acc[1][3] += a0.y * w.w;
                acc[2][0] += a0.z * w.x; acc[2][1] += a0.z * w.y; acc[2][2] += a0.z * w.z; acc[2][3] += a0.z * w.w;
                acc[3][0] += a0.w * w.x; acc[3][1] += a0.w * w.y; acc[3][2] += a0.w * w.z; acc[3][3] += a0.w * w.w;
                acc[4][0] += a1.x * w.x; acc[4][1] += a1.x * w.y; acc[4][2] += a1.x * w.z; acc[4][3] += a1.x * w.w;
                acc[5][0] += a1.y * w.x; acc[5][1] += a1.y * w.y; acc[5][2] += a1.y * w.z; acc[5][3] += a1.y * w.w;
                acc[6][0] += a1.z * w.x; acc[6][1] += a1.z * w.y; acc[6][2] += a1.z * w.z; acc[6][3] += a1.z * w.w;
                acc[7][0] += a1.w * w.x; acc[7][1] += a1.w * w.y; acc[7][2] += a1.w * w.z; acc[7][3] += a1.w * w.w;
            }
        }
        if (ch < NCH - 1) {
            float* nw = s_w1c + ((ch + 1) & 1) * (WCH * W1STRIDE);
            float* na = s_act + ((ch + 1) & 1) * (WCH * GFC);
            #pragma unroll
            for (int j = 0; j < NPREFW; j++) {
                int i = tid + j * 256;
                if (i < 2400) nw[(i % WCH) * W1STRIDE + (i / WCH)] = prw[j];
            }
            #pragma unroll
            for (int j = 0; j < NPREFA; j++) {
                int i = tid + j * 256;
                if (i < WCH * GFC) na[i] = pra[j];
            }
            if (ch < NCH - 2) {
                const int kb = (ch + 2) * WCH;
                #pragma unroll
                for (int j = 0; j < NPREFW; j++) {
                    int i = tid + j * 256;
                    if (i < 2400) prw[j] = fw1[(i / WCH) * 400 + kb + (i % WCH)];
                }
                #pragma unroll
                for (int j = 0; j < NPREFA; j++) {
                    int i = tid + j * 256;
                    if (i < WCH * GFC) pra[j] = g_actT[(size_t)(kb + i / GFC) * ACT_STRIDE + img0 + (i % GFC)];
                }
            }
        }
        __syncthreads();
    }
    if (active) {
        #pragma unroll
        for (int oo = 0; oo < 4; oo++) {
            float b = s_b1[o0 + oo];
            #pragma unroll
            for (int ii = 0; ii < 8; ii++)
                s_h1T[(o0 + oo) * GFC + i0 + ii] = fmaxf(acc[ii][oo] + b, 0.f);
        }
    }
    __syncthreads();

    // ---- fc2: [56,120] x [120,84]^T; 8img x 4out tiles; 147 active threads
    if (tid < 147) {
        int oo0 = (tid % 21) * 4;
        int ii0 = (tid / 21) * 8;
        float c2[8][4];
        #pragma unroll
        for (int i = 0; i < 8; i++)
            #pragma unroll
            for (int j = 0; j < 4; j++) c2[i][j] = 0.f;
        #pragma unroll 6
        for (int k = 0; k < 120; k++) {
            float4 w  = *reinterpret_cast<const float4*>(&s_w2T[k * 84 + oo0]);
            float4 a0 = *reinterpret_cast<const float4*>(&s_h1T[k * GFC + ii0]);
            float4 a1 = *reinterpret_cast<const float4*>(&s_h1T[k * GFC + ii0 + 4]);
            c2[0][0] += a0.x * w.x; c2[0][1] += a0.x * w.y; c2[0][2] += a0.x * w.z; c2[0][3] += a0.x * w.w;
            c2[1][0] += a0.y * w.x; c2[1][1] += a0.y * w.y; c2[1][2] += a0.y * w.z; c2[1][3] += a0.y * w.w;
            c2[2][0] += a0.z * w.x; c2[2][1] += a0.z * w.y; c2[2][2] += a0.z * w.z; c2[2][3] += a0.z * w.w;
            c2[3][0] += a0.w * w.x; c2[3][1] += a0.w * w.y; c2[3][2] += a0.w * w.z; c2[3][3] += a0.w * w.w;
            c2[4][0] += a1.x * w.x; c2[4][1] += a1.x * w.y; c2[4][2] += a1.x * w.z; c2[4][3] += a1.x * w.w;
            c2[5][0] += a1.y * w.x; c2[5][1] += a1.y * w.y; c2[5][2] += a1.y * w.z; c2[5][3] += a1.y * w.w;
            c2[6][0] += a1.z * w.x; c2[6][1] += a1.z * w.y; c2[6][2] += a1.z * w.z; c2[6][3] += a1.z * w.w;
            c2[7][0] += a1.w * w.x; c2[7][1] += a1.w * w.y; c2[7][2] += a1.w * w.z; c2[7][3] += a1.w * w.w;
        }
        #pragma unroll
        for (int ii = 0; ii < 8; ii++)
            #pragma unroll
            for (int oo = 0; oo < 4; oo++)
                s_h2[(ii0 + ii) * 84 + oo0 + oo] =
                    fmaxf(c2[ii][oo] + s_b2[oo0 + oo], 0.f);
    }
    __syncthreads();

    // ---- fc3: [56,84] x [84,10]^T -> out (guarded tail)
    for (int t = tid; t < GFC * 10; t += 256) {
        int o  = t % 10;
        int im = t / 10;
        float a = s_b3[o];
        #pragma unroll
        for (int k = 0; k < 84; k += 4) {
            float4 h = *reinterpret_cast<const float4*>(&s_h2[im * 84 + k]);
            float4 w = *reinterpret_cast<const float4*>(&s_w3[o * 84 + k]);
            a += h.x * w.x + h.y * w.y + h.z * w.z + h.w * w.w;
        }
        int gimg = img0 + im;
        if (gimg < NIMG) out[gimg * 10 + o] = a;
    }
}

extern "C" void kernel_launch(void* const* d_in, const int* in_sizes, int n_in,
                              void* d_out, int out_size)
{
    const float* x   = (const float*)d_in[0];
    const float* w1  = (const float*)d_in[1];
    const float* w2  = (const float*)d_in[2];
    const float* fw1 = (const float*)d_in[3];
    const float* fb1 = (const float*)d_in[4];
    const float* fw2 = (const float*)d_in[5];
    const float* fb2 = (const float*)d_in[6];
    const float* fw3 = (const float*)d_in[7];
    const float* fb3 = (const float*)d_in[8];
    float* out = (float*)d_out;

    const int FC_SMEM = (2 * WCH * GFC + 2 * WCH * W1STRIDE + 120 * GFC +
                         120 * 84 + 840 + 120 + 84 + 12) * (int)sizeof(float);
    cudaFuncSetAttribute(fc_kernel, cudaFuncAttributeMaxDynamicSharedMemorySize,
                         FC_SMEM);

    conv_kernel<<<NIMG / 8, 256>>>(x, w1, w2);
    fc_kernel<<<NBLK_FC, 256, FC_SMEM>>>(fw1, fb1, fw2, fb2, fw3, fb3, out);
}